// round 13
// baseline (speedup 1.0000x reference)
#include <cuda_runtime.h>
#include <cuda_fp16.h>
#include <math.h>

#define NNODE 50000
#define NEDGE 1600000

// ---------------- scratch (static device allocations; no cudaMalloc) ----------
__device__ __half g_hh[(size_t)NNODE * 128];   // h features (fp16, gather path)
__device__ float g_agg[(size_t)NNODE * 128];
__device__ float g_emb[(size_t)NNODE * 128];
__device__ float g_as[NNODE * 2];
__device__ float g_ad[NNODE * 2];
__device__ __half g_z1h[(size_t)NNODE * 512];  // z1 in fp16 (feeds MLP2 directly)
__device__ float g_z2[(size_t)NNODE * 256];
__device__ int g_rowptr[NNODE + 1];
__device__ int g_cursor[NNODE];
__device__ int g_cnt[NNODE];
__device__ int g_col[NEDGE];
__device__ int g_bsum[64];
__device__ int g_boff[64];

__device__ __forceinline__ float lrelu(float x) { return x > 0.f ? x : 0.2f * x; }

__device__ __forceinline__ unsigned f2tf(float f) {
    unsigned u;
    asm("cvt.rna.tf32.f32 %0, %1;" : "=r"(u) : "f"(f));
    return u;
}

// ---------------- CSR build ---------------------------------------------------
__global__ void zero_cnt_kernel(int n) {
    int i = blockIdx.x * blockDim.x + threadIdx.x;
    if (i < n) g_cnt[i] = 0;
}

__global__ void hist_kernel(const int* __restrict__ dst, int E) {
    int e = blockIdx.x * blockDim.x + threadIdx.x;
    if (e < E) atomicAdd(&g_cnt[dst[e]], 1);
}

__global__ void scan1_kernel(int n) {
    __shared__ int sh[1024];
    int b = blockIdx.x, tid = threadIdx.x;
    int i = b * 1024 + tid;
    int v = (i < n) ? g_cnt[i] : 0;
    sh[tid] = v;
    __syncthreads();
    for (int o = 1; o < 1024; o <<= 1) {
        int t = (tid >= o) ? sh[tid - o] : 0;
        __syncthreads();
        sh[tid] += t;
        __syncthreads();
    }
    if (i < n) g_cursor[i] = sh[tid];
    if (tid == 1023) g_bsum[b] = sh[1023];
}

__global__ void scan2_kernel(int nb, int n) {
    __shared__ int sh[64];
    int tid = threadIdx.x;
    int v = (tid < nb) ? g_bsum[tid] : 0;
    sh[tid] = v;
    __syncthreads();
    for (int o = 1; o < 64; o <<= 1) {
        int t = (tid >= o) ? sh[tid - o] : 0;
        __syncthreads();
        sh[tid] += t;
        __syncthreads();
    }
    g_boff[tid] = sh[tid] - v;
    if (tid == 63) g_rowptr[n] = sh[63];
}

__global__ void scan3_kernel(int n) {
    int i = blockIdx.x * blockDim.x + threadIdx.x;
    if (i < n) {
        int excl = g_boff[i >> 10] + g_cursor[i] - g_cnt[i];
        g_rowptr[i] = excl;
        g_cursor[i] = excl;
    }
}

__global__ void scatter_kernel(const int* __restrict__ src, const int* __restrict__ dst, int E) {
    int e = blockIdx.x * blockDim.x + threadIdx.x;
    if (e < E) {
        int d = dst[e];
        int pos = atomicAdd(&g_cursor[d], 1);
        g_col[pos] = src[e];
    }
}

// ---------------- tensor-core GEMM (tf32 HMMA): GAT layers --------------------
__global__ __launch_bounds__(256, 2) void gemm_tc_kernel(
    const float* __restrict__ A, const float* __restrict__ B,
    const float* __restrict__ bias, float* __restrict__ C,
    __half* __restrict__ Ch,
    int M, int N, int K, int relu)
{
    __shared__ unsigned As[128 * 16];
    __shared__ unsigned Bs[16 * 128];

    int tid = threadIdx.x;
    int lane = tid & 31, warp = tid >> 5;
    int wm = warp & 3, wn = warp >> 2;
    int gid = lane >> 2, ctid = lane & 3;
    int row0 = blockIdx.y * 128;
    int col0 = blockIdx.x * 128;

    int mA[2], k4A[2], kB[2], n4B[2];
#pragma unroll
    for (int i = 0; i < 2; i++) {
        int idx = tid + 256 * i;
        mA[i]  = idx >> 2;
        k4A[i] = (idx & 3) << 2;
        kB[i]  = idx >> 5;
        n4B[i] = (idx & 31) << 2;
    }

    float acc[2][8][4];
#pragma unroll
    for (int a = 0; a < 2; a++)
#pragma unroll
        for (int b = 0; b < 8; b++)
#pragma unroll
            for (int c = 0; c < 4; c++) acc[a][b][c] = 0.f;

    float4 ra[2], rb[2];
#pragma unroll
    for (int i = 0; i < 2; i++) {
        int r = row0 + mA[i];
        ra[i] = make_float4(0.f, 0.f, 0.f, 0.f);
        if (r < M) ra[i] = *(const float4*)(A + (size_t)r * K + k4A[i]);
        rb[i] = *(const float4*)(B + (size_t)kB[i] * N + col0 + n4B[i]);
    }

    for (int k0 = 0;;) {
        __syncthreads();
#pragma unroll
        for (int i = 0; i < 2; i++) {
            unsigned* pa = &As[mA[i] * 16 + (k4A[i] ^ ((mA[i] & 3) << 2))];
            pa[0] = f2tf(ra[i].x); pa[1] = f2tf(ra[i].y);
            pa[2] = f2tf(ra[i].z); pa[3] = f2tf(ra[i].w);
            unsigned* pb = &Bs[kB[i] * 128 + (n4B[i] ^ ((kB[i] & 3) << 3))];
            pb[0] = f2tf(rb[i].x); pb[1] = f2tf(rb[i].y);
            pb[2] = f2tf(rb[i].z); pb[3] = f2tf(rb[i].w);
        }
        __syncthreads();

        bool more = (k0 + 16 < K);
        if (more) {
            int kn = k0 + 16;
#pragma unroll
            for (int i = 0; i < 2; i++) {
                int r = row0 + mA[i];
                ra[i] = make_float4(0.f, 0.f, 0.f, 0.f);
                if (r < M) ra[i] = *(const float4*)(A + (size_t)r * K + kn + k4A[i]);
                rb[i] = *(const float4*)(B + (size_t)(kn + kB[i]) * N + col0 + n4B[i]);
            }
        }

#pragma unroll
        for (int ks = 0; ks < 2; ks++) {
            int kk = ks * 8;
            unsigned afr[2][4];
#pragma unroll
            for (int mf = 0; mf < 2; mf++) {
                int r = wm * 32 + mf * 16 + gid;
                int c0 = (kk + ctid) ^ ((r & 3) << 2);
                afr[mf][0] = As[r * 16 + c0];
                afr[mf][1] = As[(r + 8) * 16 + c0];
                afr[mf][2] = As[r * 16 + (c0 ^ 4)];
                afr[mf][3] = As[(r + 8) * 16 + (c0 ^ 4)];
            }
            unsigned bfr[8][2];
#pragma unroll
            for (int nf = 0; nf < 8; nf++) {
                int n = wn * 64 + nf * 8 + gid;
                int kr = kk + ctid;
                int cb = n ^ (ctid << 3);
                bfr[nf][0] = Bs[kr * 128 + cb];
                bfr[nf][1] = Bs[(kr + 4) * 128 + cb];
            }
#pragma unroll
            for (int mf = 0; mf < 2; mf++)
#pragma unroll
                for (int nf = 0; nf < 8; nf++) {
                    asm volatile(
                        "mma.sync.aligned.m16n8k8.row.col.f32.tf32.tf32.f32 "
                        "{%0,%1,%2,%3},{%4,%5,%6,%7},{%8,%9},{%0,%1,%2,%3};"
                        : "+f"(acc[mf][nf][0]), "+f"(acc[mf][nf][1]),
                          "+f"(acc[mf][nf][2]), "+f"(acc[mf][nf][3])
                        : "r"(afr[mf][0]), "r"(afr[mf][1]),
                          "r"(afr[mf][2]), "r"(afr[mf][3]),
                          "r"(bfr[nf][0]), "r"(bfr[nf][1]));
                }
        }
        k0 += 16;
        if (!more) break;
    }

#pragma unroll
    for (int mf = 0; mf < 2; mf++) {
        int r0 = row0 + wm * 32 + mf * 16 + gid;
#pragma unroll
        for (int nf = 0; nf < 8; nf++) {
            int c = col0 + wn * 64 + nf * 8 + 2 * ctid;
            float bx = 0.f, by = 0.f;
            if (bias) { bx = bias[c]; by = bias[c + 1]; }
            if (Ch) {
                if (r0 < M)
                    *(__half2*)(Ch + (size_t)r0 * N + c) =
                        __floats2half2_rn(acc[mf][nf][0], acc[mf][nf][1]);
                if (r0 + 8 < M)
                    *(__half2*)(Ch + (size_t)(r0 + 8) * N + c) =
                        __floats2half2_rn(acc[mf][nf][2], acc[mf][nf][3]);
            } else {
                if (r0 < M) {
                    float2 v;
                    v.x = acc[mf][nf][0] + bx;
                    v.y = acc[mf][nf][1] + by;
                    if (relu) { v.x = fmaxf(v.x, 0.f); v.y = fmaxf(v.y, 0.f); }
                    *(float2*)(C + (size_t)r0 * N + c) = v;
                }
                if (r0 + 8 < M) {
                    float2 v;
                    v.x = acc[mf][nf][2] + bx;
                    v.y = acc[mf][nf][3] + by;
                    if (relu) { v.x = fmaxf(v.x, 0.f); v.y = fmaxf(v.y, 0.f); }
                    *(float2*)(C + (size_t)(r0 + 8) * N + c) = v;
                }
            }
        }
    }
}

// ---------------- fp16 tensor-core GEMM (m16n8k16 HMMA): MLP layers -----------
__global__ __launch_bounds__(256, 2) void gemm_fp16_kernel(
    const float* __restrict__ Af, const __half* __restrict__ Ah,
    const float* __restrict__ B, const float* __restrict__ bias,
    float* __restrict__ C, __half* __restrict__ Ch,
    int M, int N, int K, int relu)
{
    __shared__ __half2 As2[128 * 8];    // [m][kp'], kp' = kp ^ (m&7)
    __shared__ __half2 Bt2[128 * 12];   // [n][kp], row stride 12 half2
    __half* Bth = (__half*)Bt2;

    int tid = threadIdx.x;
    int lane = tid & 31, warp = tid >> 5;
    int wm = warp & 3, wn = warp >> 2;
    int gid = lane >> 2, ctid = lane & 3;
    int row0 = blockIdx.y * 128;
    int col0 = blockIdx.x * 128;

    int mA = tid >> 1;
    int kpA = (tid & 1) * 4;        // half2 offset; halfs offset = kpA*2 (0 or 8)
    int kB[2], n4B[2];
#pragma unroll
    for (int i = 0; i < 2; i++) {
        int idx = tid + 256 * i;
        kB[i] = idx >> 5;
        n4B[i] = (idx & 31) << 2;
    }

    float acc[2][8][4];
#pragma unroll
    for (int a = 0; a < 2; a++)
#pragma unroll
        for (int b = 0; b < 8; b++)
#pragma unroll
            for (int c = 0; c < 4; c++) acc[a][b][c] = 0.f;

    __half2 rah[4];
    float4 rbf[2];

    // prefetch tile 0
    {
        int r = row0 + mA;
        if (Ah) {
            uint4 u = make_uint4(0u, 0u, 0u, 0u);   // 16 bytes = 8 halfs
            if (r < M) u = *(const uint4*)(Ah + (size_t)r * K + kpA * 2);
            rah[0] = *(__half2*)&u.x; rah[1] = *(__half2*)&u.y;
            rah[2] = *(__half2*)&u.z; rah[3] = *(__half2*)&u.w;
        } else {
            float4 f0 = make_float4(0.f, 0.f, 0.f, 0.f), f1 = f0;
            if (r < M) {
                f0 = *(const float4*)(Af + (size_t)r * K + kpA * 2);
                f1 = *(const float4*)(Af + (size_t)r * K + kpA * 2 + 4);
            }
            rah[0] = __floats2half2_rn(f0.x, f0.y);
            rah[1] = __floats2half2_rn(f0.z, f0.w);
            rah[2] = __floats2half2_rn(f1.x, f1.y);
            rah[3] = __floats2half2_rn(f1.z, f1.w);
        }
#pragma unroll
        for (int i = 0; i < 2; i++)
            rbf[i] = *(const float4*)(B + (size_t)kB[i] * N + col0 + n4B[i]);
    }

    for (int k0 = 0;;) {
        __syncthreads();
#pragma unroll
        for (int j = 0; j < 4; j++) {
            int kp = kpA + j;
            As2[mA * 8 + (kp ^ (mA & 7))] = rah[j];
        }
#pragma unroll
        for (int i = 0; i < 2; i++) {
            int k = kB[i];
            Bth[(n4B[i] + 0) * 24 + k] = __float2half_rn(rbf[i].x);
            Bth[(n4B[i] + 1) * 24 + k] = __float2half_rn(rbf[i].y);
            Bth[(n4B[i] + 2) * 24 + k] = __float2half_rn(rbf[i].z);
            Bth[(n4B[i] + 3) * 24 + k] = __float2half_rn(rbf[i].w);
        }
        __syncthreads();

        bool more = (k0 + 16 < K);
        if (more) {
            int kn = k0 + 16;
            int r = row0 + mA;
            if (Ah) {
                uint4 u = make_uint4(0u, 0u, 0u, 0u);   // 16 bytes = 8 halfs
                if (r < M) u = *(const uint4*)(Ah + (size_t)r * K + kn + kpA * 2);
                rah[0] = *(__half2*)&u.x; rah[1] = *(__half2*)&u.y;
                rah[2] = *(__half2*)&u.z; rah[3] = *(__half2*)&u.w;
            } else {
                float4 f0 = make_float4(0.f, 0.f, 0.f, 0.f), f1 = f0;
                if (r < M) {
                    f0 = *(const float4*)(Af + (size_t)r * K + kn + kpA * 2);
                    f1 = *(const float4*)(Af + (size_t)r * K + kn + kpA * 2 + 4);
                }
                rah[0] = __floats2half2_rn(f0.x, f0.y);
                rah[1] = __floats2half2_rn(f0.z, f0.w);
                rah[2] = __floats2half2_rn(f1.x, f1.y);
                rah[3] = __floats2half2_rn(f1.z, f1.w);
            }
#pragma unroll
            for (int i = 0; i < 2; i++)
                rbf[i] = *(const float4*)(B + (size_t)(kn + kB[i]) * N + col0 + n4B[i]);
        }

        unsigned afr[2][4];
#pragma unroll
        for (int mf = 0; mf < 2; mf++) {
            int r = wm * 32 + mf * 16 + gid;
            afr[mf][0] = *(unsigned*)&As2[r * 8 + (ctid ^ (r & 7))];
            afr[mf][1] = *(unsigned*)&As2[(r + 8) * 8 + (ctid ^ ((r + 8) & 7))];
            afr[mf][2] = *(unsigned*)&As2[r * 8 + ((ctid + 4) ^ (r & 7))];
            afr[mf][3] = *(unsigned*)&As2[(r + 8) * 8 + ((ctid + 4) ^ ((r + 8) & 7))];
        }
        unsigned bfr[8][2];
#pragma unroll
        for (int nf = 0; nf < 8; nf++) {
            int n = wn * 64 + nf * 8 + gid;
            bfr[nf][0] = *(unsigned*)&Bt2[n * 12 + ctid];
            bfr[nf][1] = *(unsigned*)&Bt2[n * 12 + ctid + 4];
        }
#pragma unroll
        for (int mf = 0; mf < 2; mf++)
#pragma unroll
            for (int nf = 0; nf < 8; nf++) {
                asm volatile(
                    "mma.sync.aligned.m16n8k16.row.col.f32.f16.f16.f32 "
                    "{%0,%1,%2,%3},{%4,%5,%6,%7},{%8,%9},{%0,%1,%2,%3};"
                    : "+f"(acc[mf][nf][0]), "+f"(acc[mf][nf][1]),
                      "+f"(acc[mf][nf][2]), "+f"(acc[mf][nf][3])
                    : "r"(afr[mf][0]), "r"(afr[mf][1]),
                      "r"(afr[mf][2]), "r"(afr[mf][3]),
                      "r"(bfr[nf][0]), "r"(bfr[nf][1]));
            }
        k0 += 16;
        if (!more) break;
    }

#pragma unroll
    for (int mf = 0; mf < 2; mf++) {
        int r0 = row0 + wm * 32 + mf * 16 + gid;
#pragma unroll
        for (int nf = 0; nf < 8; nf++) {
            int c = col0 + wn * 64 + nf * 8 + 2 * ctid;
            float bx = 0.f, by = 0.f;
            if (bias) { bx = bias[c]; by = bias[c + 1]; }
            float v0 = acc[mf][nf][0] + bx, v1 = acc[mf][nf][1] + by;
            float v2 = acc[mf][nf][2] + bx, v3 = acc[mf][nf][3] + by;
            if (relu) {
                v0 = fmaxf(v0, 0.f); v1 = fmaxf(v1, 0.f);
                v2 = fmaxf(v2, 0.f); v3 = fmaxf(v3, 0.f);
            }
            if (Ch) {
                if (r0 < M)
                    *(__half2*)(Ch + (size_t)r0 * N + c) = __floats2half2_rn(v0, v1);
                if (r0 + 8 < M)
                    *(__half2*)(Ch + (size_t)(r0 + 8) * N + c) = __floats2half2_rn(v2, v3);
            } else {
                if (r0 < M) *(float2*)(C + (size_t)r0 * N + c) = make_float2(v0, v1);
                if (r0 + 8 < M) *(float2*)(C + (size_t)(r0 + 8) * N + c) = make_float2(v2, v3);
            }
        }
    }
}

// ---------------- small GEMM for logits: N=16, K<=256 -------------------------
__global__ __launch_bounds__(128) void gemm_logits_kernel(
    const float* __restrict__ A, const float* __restrict__ B,
    const float* __restrict__ bias, float* __restrict__ C, int M, int K)
{
    __shared__ float Bs[256 * 16];
    __shared__ float As[8][256];
    int tid = threadIdx.x;
    for (int idx = tid; idx < K * 16; idx += 128) Bs[idx] = B[idx];
    int row0 = blockIdx.x * 8;
    int nf4 = (8 * K) / 4;
    for (int idx = tid; idx < nf4; idx += 128) {
        int r = (idx * 4) / K;
        int k = (idx * 4) % K;
        float4 v = make_float4(0.f, 0.f, 0.f, 0.f);
        if (row0 + r < M) v = *(const float4*)(A + (size_t)(row0 + r) * K + k);
        *(float4*)&As[r][k] = v;
    }
    __syncthreads();
    int r = tid >> 4;
    int c = tid & 15;
    float acc = 0.f;
    for (int k = 0; k < K; k++) acc += As[r][k] * Bs[k * 16 + c];
    if (row0 + r < M) C[(size_t)(row0 + r) * 16 + c] = acc + bias[c];
}

// ---------------- attention coefficients (half h) -----------------------------
__global__ void coeff_kernel(const __half* __restrict__ h,
                             const float* __restrict__ a_src,
                             const float* __restrict__ a_dst, int N)
{
    int t = blockIdx.x * blockDim.x + threadIdx.x;
    if (t >= N * 2) return;
    int node = t >> 1, head = t & 1;
    const __half2* hp = (const __half2*)(h + (size_t)node * 128 + head * 64);
    const float2* ap = (const float2*)(a_src + head * 64);
    const float2* dp = (const float2*)(a_dst + head * 64);
    float s = 0.f, d = 0.f;
#pragma unroll
    for (int i = 0; i < 32; i++) {
        float2 hv = __half22float2(hp[i]);
        float2 av = ap[i], bv = dp[i];
        s += hv.x * av.x + hv.y * av.y;
        d += hv.x * bv.x + hv.y * bv.y;
    }
    g_as[t] = s;
    g_ad[t] = d;
}

// ---------------- gather aggregation: one warp per dst node -------------------
__global__ __launch_bounds__(256) void aggregate_kernel(
    const __half* __restrict__ hfeat, const float* __restrict__ bias,
    float* __restrict__ outp, float* __restrict__ outp2, int N, int relu)
{
    int warp = (blockIdx.x * blockDim.x + threadIdx.x) >> 5;
    if (warp >= N) return;
    int node = warp;
    int lane = threadIdx.x & 31;
    int head = lane >> 4;
    int c = head * 64 + (lane & 15) * 4;

    const float2* as2p = (const float2*)g_as;
    float2 adn = ((const float2*)g_ad)[node];
    float2 asn = as2p[node];
    int beg = g_rowptr[node], end = g_rowptr[node + 1];

    float m0 = lrelu(asn.x + adn.x);
    float m1 = lrelu(asn.y + adn.y);
    for (int i = beg + lane; i < end; i += 32) {
        int s = g_col[i];
        float2 a = as2p[s];
        m0 = fmaxf(m0, lrelu(a.x + adn.x));
        m1 = fmaxf(m1, lrelu(a.y + adn.y));
    }
#pragma unroll
    for (int o = 16; o; o >>= 1) {
        m0 = fmaxf(m0, __shfl_xor_sync(0xffffffffu, m0, o));
        m1 = fmaxf(m1, __shfl_xor_sync(0xffffffffu, m1, o));
    }
    float m = head ? m1 : m0;
    float adh = head ? adn.y : adn.x;

    float denom = 0.f;
    float4 acc = make_float4(0.f, 0.f, 0.f, 0.f);
    {
        float e = lrelu((head ? asn.y : asn.x) + adh);
        float w = __expf(e - m);
        denom += w;
        uint2 u = *(const uint2*)(hfeat + (size_t)node * 128 + c);
        float2 p0 = __half22float2(*(__half2*)&u.x);
        float2 p1 = __half22float2(*(__half2*)&u.y);
        acc.x += w * p0.x; acc.y += w * p0.y; acc.z += w * p1.x; acc.w += w * p1.y;
    }
    for (int i = beg; i < end; i++) {
        int s = g_col[i];
        float2 a = as2p[s];
        float e = lrelu((head ? a.y : a.x) + adh);
        float w = __expf(e - m);
        denom += w;
        uint2 u = *(const uint2*)(hfeat + (size_t)s * 128 + c);
        float2 p0 = __half22float2(*(__half2*)&u.x);
        float2 p1 = __half22float2(*(__half2*)&u.y);
        acc.x += w * p0.x; acc.y += w * p0.y; acc.z += w * p1.x; acc.w += w * p1.y;
    }
    float inv = 1.f / (denom + 1e-16f);
    float4 b4 = *(const float4*)(bias + c);
    float4 o;
    o.x = acc.x * inv + b4.x;
    o.y = acc.y * inv + b4.y;
    o.z = acc.z * inv + b4.z;
    o.w = acc.w * inv + b4.w;
    if (relu) {
        o.x = fmaxf(o.x, 0.f); o.y = fmaxf(o.y, 0.f);
        o.z = fmaxf(o.z, 0.f); o.w = fmaxf(o.w, 0.f);
    }
    *(float4*)(outp + (size_t)node * 128 + c) = o;
    if (outp2) *(float4*)(outp2 + (size_t)node * 128 + c) = o;
}

// ---------------- launch ------------------------------------------------------
extern "C" void kernel_launch(void* const* d_in, const int* in_sizes, int n_in,
                              void* d_out, int out_size)
{
    const float* x   = (const float*)d_in[0];
    const int*   ei  = (const int*)d_in[1];
    const float* W1  = (const float*)d_in[2];
    const float* a_s1 = (const float*)d_in[3];
    const float* a_d1 = (const float*)d_in[4];
    const float* b1  = (const float*)d_in[5];
    const float* W2  = (const float*)d_in[6];
    const float* a_s2 = (const float*)d_in[7];
    const float* a_d2 = (const float*)d_in[8];
    const float* b2  = (const float*)d_in[9];
    const float* lw1 = (const float*)d_in[10];
    const float* lb1 = (const float*)d_in[11];
    const float* lw2 = (const float*)d_in[12];
    const float* lb2 = (const float*)d_in[13];
    const float* lw3 = (const float*)d_in[14];
    const float* lb3 = (const float*)d_in[15];
    float* dout = (float*)d_out;

    int N = in_sizes[0] / 64;
    int E = in_sizes[1] / 2;

    __half *p_hh, *p_z1h;
    float *p_agg, *p_emb, *p_z2;
    cudaGetSymbolAddress((void**)&p_hh, g_hh);
    cudaGetSymbolAddress((void**)&p_agg, g_agg);
    cudaGetSymbolAddress((void**)&p_emb, g_emb);
    cudaGetSymbolAddress((void**)&p_z1h, g_z1h);
    cudaGetSymbolAddress((void**)&p_z2, g_z2);

    const int* src = ei;
    const int* dst = ei + E;

    // --- CSR build ---
    int nb = (N + 1023) / 1024;
    zero_cnt_kernel<<<(N + 255) / 256, 256>>>(N);
    hist_kernel<<<(E + 255) / 256, 256>>>(dst, E);
    scan1_kernel<<<nb, 1024>>>(N);
    scan2_kernel<<<1, 64>>>(nb, N);
    scan3_kernel<<<(N + 255) / 256, 256>>>(N);
    scatter_kernel<<<(E + 255) / 256, 256>>>(src, dst, E);

    int mblk = (N + 127) / 128;

    // output layout: [emb (N*128), logits (N*16)]
    size_t embElems = (size_t)N * 128;
    bool both = (size_t)out_size >= embElems + (size_t)N * 16;
    float* logits_out = both ? (dout + embElems)
                             : (dout + ((size_t)out_size - (size_t)N * 16));
    float* embMirror = both ? dout : nullptr;   // write-only stream into d_out

    // --- GAT layer 1 (h in fp16) ---
    gemm_tc_kernel<<<dim3(1, mblk), 256>>>(x, W1, nullptr, nullptr, p_hh, N, 128, 64, 0);
    coeff_kernel<<<(2 * N + 255) / 256, 256>>>(p_hh, a_s1, a_d1, N);
    aggregate_kernel<<<(N + 7) / 8, 256>>>(p_hh, b1, p_agg, nullptr, N, 1);

    // --- GAT layer 2 (emb -> device scratch + write-only mirror into d_out) ---
    gemm_tc_kernel<<<dim3(1, mblk), 256>>>(p_agg, W2, nullptr, nullptr, p_hh, N, 128, 128, 0);
    coeff_kernel<<<(2 * N + 255) / 256, 256>>>(p_hh, a_s2, a_d2, N);
    aggregate_kernel<<<(N + 7) / 8, 256>>>(p_hh, b2, p_emb, embMirror, N, 1);

    // --- MLP head (fp16 tensor cores; z1 kept fp16) ---
    gemm_fp16_kernel<<<dim3(4, mblk), 256>>>(p_emb, nullptr, lw1, lb1, nullptr, p_z1h, N, 512, 128, 1);
    gemm_fp16_kernel<<<dim3(2, mblk), 256>>>(nullptr, p_z1h, lw2, lb2, p_z2, nullptr, N, 256, 512, 1);
    gemm_logits_kernel<<<(N + 7) / 8, 128>>>(p_z2, lw3, lb3, logits_out, N, 256);
}

// round 15
// speedup vs baseline: 1.3562x; 1.3562x over previous
#include <cuda_runtime.h>
#include <cuda_fp16.h>
#include <math.h>

#define NNODE 50000
#define NEDGE 1600000

// ---------------- scratch (static device allocations; no cudaMalloc) ----------
__device__ __half g_hh[(size_t)NNODE * 128];   // h features (fp16, gather path)
__device__ float g_agg[(size_t)NNODE * 128];
__device__ float g_emb[(size_t)NNODE * 128];
__device__ float g_as[NNODE * 2];
__device__ float g_ad[NNODE * 2];
__device__ __half g_z1h[(size_t)NNODE * 512];  // z1 in fp16 (feeds MLP2 directly)
__device__ float g_z2[(size_t)NNODE * 256];
__device__ int g_rowptr[NNODE + 1];
__device__ int g_cursor[NNODE];
__device__ int g_cnt[NNODE];
__device__ int g_col[NEDGE];
__device__ int g_bsum[64];
__device__ int g_boff[64];

__device__ __forceinline__ float lrelu(float x) { return x > 0.f ? x : 0.2f * x; }

__device__ __forceinline__ unsigned f2tf(float f) {
    unsigned u;
    asm("cvt.rna.tf32.f32 %0, %1;" : "=r"(u) : "f"(f));
    return u;
}

#define LDSM_X4_TRANS(r0, r1, r2, r3, addr) \
    asm volatile("ldmatrix.sync.aligned.m8n8.x4.trans.shared.b16 {%0,%1,%2,%3}, [%4];" \
        : "=r"(r0), "=r"(r1), "=r"(r2), "=r"(r3) : "r"(addr))

// ---------------- CSR build ---------------------------------------------------
__global__ void zero_cnt_kernel(int n) {
    int i = blockIdx.x * blockDim.x + threadIdx.x;
    if (i < n) g_cnt[i] = 0;
}

__global__ void hist_kernel(const int* __restrict__ dst, int E) {
    int e = blockIdx.x * blockDim.x + threadIdx.x;
    if (e < E) atomicAdd(&g_cnt[dst[e]], 1);
}

__global__ void scan1_kernel(int n) {
    __shared__ int sh[1024];
    int b = blockIdx.x, tid = threadIdx.x;
    int i = b * 1024 + tid;
    int v = (i < n) ? g_cnt[i] : 0;
    sh[tid] = v;
    __syncthreads();
    for (int o = 1; o < 1024; o <<= 1) {
        int t = (tid >= o) ? sh[tid - o] : 0;
        __syncthreads();
        sh[tid] += t;
        __syncthreads();
    }
    if (i < n) g_cursor[i] = sh[tid];
    if (tid == 1023) g_bsum[b] = sh[1023];
}

__global__ void scan2_kernel(int nb, int n) {
    __shared__ int sh[64];
    int tid = threadIdx.x;
    int v = (tid < nb) ? g_bsum[tid] : 0;
    sh[tid] = v;
    __syncthreads();
    for (int o = 1; o < 64; o <<= 1) {
        int t = (tid >= o) ? sh[tid - o] : 0;
        __syncthreads();
        sh[tid] += t;
        __syncthreads();
    }
    g_boff[tid] = sh[tid] - v;
    if (tid == 63) g_rowptr[n] = sh[63];
}

__global__ void scan3_kernel(int n) {
    int i = blockIdx.x * blockDim.x + threadIdx.x;
    if (i < n) {
        int excl = g_boff[i >> 10] + g_cursor[i] - g_cnt[i];
        g_rowptr[i] = excl;
        g_cursor[i] = excl;
    }
}

__global__ void scatter_kernel(const int* __restrict__ src, const int* __restrict__ dst, int E) {
    int e = blockIdx.x * blockDim.x + threadIdx.x;
    if (e < E) {
        int d = dst[e];
        int pos = atomicAdd(&g_cursor[d], 1);
        g_col[pos] = src[e];
    }
}

// ---------------- tensor-core GEMM (tf32 HMMA): GAT layers --------------------
__global__ __launch_bounds__(256, 2) void gemm_tc_kernel(
    const float* __restrict__ A, const float* __restrict__ B,
    const float* __restrict__ bias, float* __restrict__ C,
    __half* __restrict__ Ch,
    int M, int N, int K, int relu)
{
    __shared__ unsigned As[128 * 16];
    __shared__ unsigned Bs[16 * 128];

    int tid = threadIdx.x;
    int lane = tid & 31, warp = tid >> 5;
    int wm = warp & 3, wn = warp >> 2;
    int gid = lane >> 2, ctid = lane & 3;
    int row0 = blockIdx.y * 128;
    int col0 = blockIdx.x * 128;

    int mA[2], k4A[2], kB[2], n4B[2];
#pragma unroll
    for (int i = 0; i < 2; i++) {
        int idx = tid + 256 * i;
        mA[i]  = idx >> 2;
        k4A[i] = (idx & 3) << 2;
        kB[i]  = idx >> 5;
        n4B[i] = (idx & 31) << 2;
    }

    float acc[2][8][4];
#pragma unroll
    for (int a = 0; a < 2; a++)
#pragma unroll
        for (int b = 0; b < 8; b++)
#pragma unroll
            for (int c = 0; c < 4; c++) acc[a][b][c] = 0.f;

    float4 ra[2], rb[2];
#pragma unroll
    for (int i = 0; i < 2; i++) {
        int r = row0 + mA[i];
        ra[i] = make_float4(0.f, 0.f, 0.f, 0.f);
        if (r < M) ra[i] = *(const float4*)(A + (size_t)r * K + k4A[i]);
        rb[i] = *(const float4*)(B + (size_t)kB[i] * N + col0 + n4B[i]);
    }

    for (int k0 = 0;;) {
        __syncthreads();
#pragma unroll
        for (int i = 0; i < 2; i++) {
            unsigned* pa = &As[mA[i] * 16 + (k4A[i] ^ ((mA[i] & 3) << 2))];
            pa[0] = f2tf(ra[i].x); pa[1] = f2tf(ra[i].y);
            pa[2] = f2tf(ra[i].z); pa[3] = f2tf(ra[i].w);
            unsigned* pb = &Bs[kB[i] * 128 + (n4B[i] ^ ((kB[i] & 3) << 3))];
            pb[0] = f2tf(rb[i].x); pb[1] = f2tf(rb[i].y);
            pb[2] = f2tf(rb[i].z); pb[3] = f2tf(rb[i].w);
        }
        __syncthreads();

        bool more = (k0 + 16 < K);
        if (more) {
            int kn = k0 + 16;
#pragma unroll
            for (int i = 0; i < 2; i++) {
                int r = row0 + mA[i];
                ra[i] = make_float4(0.f, 0.f, 0.f, 0.f);
                if (r < M) ra[i] = *(const float4*)(A + (size_t)r * K + kn + k4A[i]);
                rb[i] = *(const float4*)(B + (size_t)(kn + kB[i]) * N + col0 + n4B[i]);
            }
        }

#pragma unroll
        for (int ks = 0; ks < 2; ks++) {
            int kk = ks * 8;
            unsigned afr[2][4];
#pragma unroll
            for (int mf = 0; mf < 2; mf++) {
                int r = wm * 32 + mf * 16 + gid;
                int c0 = (kk + ctid) ^ ((r & 3) << 2);
                afr[mf][0] = As[r * 16 + c0];
                afr[mf][1] = As[(r + 8) * 16 + c0];
                afr[mf][2] = As[r * 16 + (c0 ^ 4)];
                afr[mf][3] = As[(r + 8) * 16 + (c0 ^ 4)];
            }
            unsigned bfr[8][2];
#pragma unroll
            for (int nf = 0; nf < 8; nf++) {
                int n = wn * 64 + nf * 8 + gid;
                int kr = kk + ctid;
                int cb = n ^ (ctid << 3);
                bfr[nf][0] = Bs[kr * 128 + cb];
                bfr[nf][1] = Bs[(kr + 4) * 128 + cb];
            }
#pragma unroll
            for (int mf = 0; mf < 2; mf++)
#pragma unroll
                for (int nf = 0; nf < 8; nf++) {
                    asm volatile(
                        "mma.sync.aligned.m16n8k8.row.col.f32.tf32.tf32.f32 "
                        "{%0,%1,%2,%3},{%4,%5,%6,%7},{%8,%9},{%0,%1,%2,%3};"
                        : "+f"(acc[mf][nf][0]), "+f"(acc[mf][nf][1]),
                          "+f"(acc[mf][nf][2]), "+f"(acc[mf][nf][3])
                        : "r"(afr[mf][0]), "r"(afr[mf][1]),
                          "r"(afr[mf][2]), "r"(afr[mf][3]),
                          "r"(bfr[nf][0]), "r"(bfr[nf][1]));
                }
        }
        k0 += 16;
        if (!more) break;
    }

#pragma unroll
    for (int mf = 0; mf < 2; mf++) {
        int r0 = row0 + wm * 32 + mf * 16 + gid;
#pragma unroll
        for (int nf = 0; nf < 8; nf++) {
            int c = col0 + wn * 64 + nf * 8 + 2 * ctid;
            float bx = 0.f, by = 0.f;
            if (bias) { bx = bias[c]; by = bias[c + 1]; }
            if (Ch) {
                if (r0 < M)
                    *(__half2*)(Ch + (size_t)r0 * N + c) =
                        __floats2half2_rn(acc[mf][nf][0], acc[mf][nf][1]);
                if (r0 + 8 < M)
                    *(__half2*)(Ch + (size_t)(r0 + 8) * N + c) =
                        __floats2half2_rn(acc[mf][nf][2], acc[mf][nf][3]);
            } else {
                if (r0 < M) {
                    float2 v;
                    v.x = acc[mf][nf][0] + bx;
                    v.y = acc[mf][nf][1] + by;
                    if (relu) { v.x = fmaxf(v.x, 0.f); v.y = fmaxf(v.y, 0.f); }
                    *(float2*)(C + (size_t)r0 * N + c) = v;
                }
                if (r0 + 8 < M) {
                    float2 v;
                    v.x = acc[mf][nf][2] + bx;
                    v.y = acc[mf][nf][3] + by;
                    if (relu) { v.x = fmaxf(v.x, 0.f); v.y = fmaxf(v.y, 0.f); }
                    *(float2*)(C + (size_t)(r0 + 8) * N + c) = v;
                }
            }
        }
    }
}

// ---------------- fp16 tensor-core GEMM (m16n8k16 HMMA): MLP layers -----------
// A smem: half2 [m][8] with column swizzle kp^(m&7) (conflict-free frags).
// B smem: row-major [k][136 halfs] (272B rows -> ldmatrix rows hit distinct
// banks); fragments via ldmatrix.x4.trans (canonical k-major B idiom).
__global__ __launch_bounds__(256, 2) void gemm_fp16_kernel(
    const float* __restrict__ Af, const __half* __restrict__ Ah,
    const float* __restrict__ B, const float* __restrict__ bias,
    float* __restrict__ C, __half* __restrict__ Ch,
    int M, int N, int K, int relu)
{
    __shared__ __half2 As2[128 * 8];    // [m][kp'], kp' = kp ^ (m&7)
    __shared__ __half Bh[16 * 136];     // [k][n], padded row stride 136 halfs

    int tid = threadIdx.x;
    int lane = tid & 31, warp = tid >> 5;
    int wm = warp & 3, wn = warp >> 2;
    int gid = lane >> 2, ctid = lane & 3;
    int row0 = blockIdx.y * 128;
    int col0 = blockIdx.x * 128;

    int mA = tid >> 1;
    int kpA = (tid & 1) * 4;        // half2 offset; halfs offset = kpA*2 (0 or 8)
    int kB[2], n4B[2];
#pragma unroll
    for (int i = 0; i < 2; i++) {
        int idx = tid + 256 * i;
        kB[i] = idx >> 5;
        n4B[i] = (idx & 31) << 2;
    }

    // ldmatrix lane address: matrix (lane>>3)&1 selects k-half, lane>>4 selects n-octet
    int kr  = ((lane >> 3) & 1) * 8 + (lane & 7);
    int ncl = (lane >> 4) * 8;
    unsigned bbase = (unsigned)__cvta_generic_to_shared(Bh) + (unsigned)((kr * 136 + ncl) * 2);

    float acc[2][8][4];
#pragma unroll
    for (int a = 0; a < 2; a++)
#pragma unroll
        for (int b = 0; b < 8; b++)
#pragma unroll
            for (int c = 0; c < 4; c++) acc[a][b][c] = 0.f;

    __half2 rah[4];
    float4 rbf[2];

    // prefetch tile 0
    {
        int r = row0 + mA;
        if (Ah) {
            uint4 u = make_uint4(0u, 0u, 0u, 0u);   // 16 bytes = 8 halfs
            if (r < M) u = *(const uint4*)(Ah + (size_t)r * K + kpA * 2);
            rah[0] = *(__half2*)&u.x; rah[1] = *(__half2*)&u.y;
            rah[2] = *(__half2*)&u.z; rah[3] = *(__half2*)&u.w;
        } else {
            float4 f0 = make_float4(0.f, 0.f, 0.f, 0.f), f1 = f0;
            if (r < M) {
                f0 = *(const float4*)(Af + (size_t)r * K + kpA * 2);
                f1 = *(const float4*)(Af + (size_t)r * K + kpA * 2 + 4);
            }
            rah[0] = __floats2half2_rn(f0.x, f0.y);
            rah[1] = __floats2half2_rn(f0.z, f0.w);
            rah[2] = __floats2half2_rn(f1.x, f1.y);
            rah[3] = __floats2half2_rn(f1.z, f1.w);
        }
#pragma unroll
        for (int i = 0; i < 2; i++)
            rbf[i] = *(const float4*)(B + (size_t)kB[i] * N + col0 + n4B[i]);
    }

    for (int k0 = 0;;) {
        __syncthreads();
#pragma unroll
        for (int j = 0; j < 4; j++) {
            int kp = kpA + j;
            As2[mA * 8 + (kp ^ (mA & 7))] = rah[j];
        }
        // B: row-major half2 stores (8B, coalesced, conflict-free)
#pragma unroll
        for (int i = 0; i < 2; i++) {
            int k = kB[i];
            __half2 h0 = __floats2half2_rn(rbf[i].x, rbf[i].y);
            __half2 h1 = __floats2half2_rn(rbf[i].z, rbf[i].w);
            uint2 pk;
            pk.x = *(unsigned*)&h0;
            pk.y = *(unsigned*)&h1;
            *(uint2*)&Bh[k * 136 + n4B[i]] = pk;
        }
        __syncthreads();

        bool more = (k0 + 16 < K);
        if (more) {
            int kn = k0 + 16;
            int r = row0 + mA;
            if (Ah) {
                uint4 u = make_uint4(0u, 0u, 0u, 0u);
                if (r < M) u = *(const uint4*)(Ah + (size_t)r * K + kn + kpA * 2);
                rah[0] = *(__half2*)&u.x; rah[1] = *(__half2*)&u.y;
                rah[2] = *(__half2*)&u.z; rah[3] = *(__half2*)&u.w;
            } else {
                float4 f0 = make_float4(0.f, 0.f, 0.f, 0.f), f1 = f0;
                if (r < M) {
                    f0 = *(const float4*)(Af + (size_t)r * K + kn + kpA * 2);
                    f1 = *(const float4*)(Af + (size_t)r * K + kn + kpA * 2 + 4);
                }
                rah[0] = __floats2half2_rn(f0.x, f0.y);
                rah[1] = __floats2half2_rn(f0.z, f0.w);
                rah[2] = __floats2half2_rn(f1.x, f1.y);
                rah[3] = __floats2half2_rn(f1.z, f1.w);
            }
#pragma unroll
            for (int i = 0; i < 2; i++)
                rbf[i] = *(const float4*)(B + (size_t)(kn + kB[i]) * N + col0 + n4B[i]);
        }

        unsigned afr[2][4];
#pragma unroll
        for (int mf = 0; mf < 2; mf++) {
            int r = wm * 32 + mf * 16 + gid;
            afr[mf][0] = *(unsigned*)&As2[r * 8 + (ctid ^ (r & 7))];
            afr[mf][1] = *(unsigned*)&As2[(r + 8) * 8 + (ctid ^ ((r + 8) & 7))];
            afr[mf][2] = *(unsigned*)&As2[r * 8 + ((ctid + 4) ^ (r & 7))];
            afr[mf][3] = *(unsigned*)&As2[(r + 8) * 8 + ((ctid + 4) ^ ((r + 8) & 7))];
        }
        unsigned bfr[8][2];
#pragma unroll
        for (int p = 0; p < 4; p++) {
            unsigned sa = bbase + (unsigned)((wn * 64 + p * 16) * 2);
            LDSM_X4_TRANS(bfr[2 * p][0], bfr[2 * p][1],
                          bfr[2 * p + 1][0], bfr[2 * p + 1][1], sa);
        }
#pragma unroll
        for (int mf = 0; mf < 2; mf++)
#pragma unroll
            for (int nf = 0; nf < 8; nf++) {
                asm volatile(
                    "mma.sync.aligned.m16n8k16.row.col.f32.f16.f16.f32 "
                    "{%0,%1,%2,%3},{%4,%5,%6,%7},{%8,%9},{%0,%1,%2,%3};"
                    : "+f"(acc[mf][nf][0]), "+f"(acc[mf][nf][1]),
                      "+f"(acc[mf][nf][2]), "+f"(acc[mf][nf][3])
                    : "r"(afr[mf][0]), "r"(afr[mf][1]),
                      "r"(afr[mf][2]), "r"(afr[mf][3]),
                      "r"(bfr[nf][0]), "r"(bfr[nf][1]));
            }
        k0 += 16;
        if (!more) break;
    }

#pragma unroll
    for (int mf = 0; mf < 2; mf++) {
        int r0 = row0 + wm * 32 + mf * 16 + gid;
#pragma unroll
        for (int nf = 0; nf < 8; nf++) {
            int c = col0 + wn * 64 + nf * 8 + 2 * ctid;
            float bx = 0.f, by = 0.f;
            if (bias) { bx = bias[c]; by = bias[c + 1]; }
            float v0 = acc[mf][nf][0] + bx, v1 = acc[mf][nf][1] + by;
            float v2 = acc[mf][nf][2] + bx, v3 = acc[mf][nf][3] + by;
            if (relu) {
                v0 = fmaxf(v0, 0.f); v1 = fmaxf(v1, 0.f);
                v2 = fmaxf(v2, 0.f); v3 = fmaxf(v3, 0.f);
            }
            if (Ch) {
                if (r0 < M)
                    *(__half2*)(Ch + (size_t)r0 * N + c) = __floats2half2_rn(v0, v1);
                if (r0 + 8 < M)
                    *(__half2*)(Ch + (size_t)(r0 + 8) * N + c) = __floats2half2_rn(v2, v3);
            } else {
                if (r0 < M) *(float2*)(C + (size_t)r0 * N + c) = make_float2(v0, v1);
                if (r0 + 8 < M) *(float2*)(C + (size_t)(r0 + 8) * N + c) = make_float2(v2, v3);
            }
        }
    }
}

// ---------------- small GEMM for logits: N=16, K<=256 -------------------------
__global__ __launch_bounds__(128) void gemm_logits_kernel(
    const float* __restrict__ A, const float* __restrict__ B,
    const float* __restrict__ bias, float* __restrict__ C, int M, int K)
{
    __shared__ float Bs[256 * 16];
    __shared__ float As[8][256];
    int tid = threadIdx.x;
    for (int idx = tid; idx < K * 16; idx += 128) Bs[idx] = B[idx];
    int row0 = blockIdx.x * 8;
    int nf4 = (8 * K) / 4;
    for (int idx = tid; idx < nf4; idx += 128) {
        int r = (idx * 4) / K;
        int k = (idx * 4) % K;
        float4 v = make_float4(0.f, 0.f, 0.f, 0.f);
        if (row0 + r < M) v = *(const float4*)(A + (size_t)(row0 + r) * K + k);
        *(float4*)&As[r][k] = v;
    }
    __syncthreads();
    int r = tid >> 4;
    int c = tid & 15;
    float acc = 0.f;
    for (int k = 0; k < K; k++) acc += As[r][k] * Bs[k * 16 + c];
    if (row0 + r < M) C[(size_t)(row0 + r) * 16 + c] = acc + bias[c];
}

// ---------------- attention coefficients (half h) -----------------------------
__global__ void coeff_kernel(const __half* __restrict__ h,
                             const float* __restrict__ a_src,
                             const float* __restrict__ a_dst, int N)
{
    int t = blockIdx.x * blockDim.x + threadIdx.x;
    if (t >= N * 2) return;
    int node = t >> 1, head = t & 1;
    const __half2* hp = (const __half2*)(h + (size_t)node * 128 + head * 64);
    const float2* ap = (const float2*)(a_src + head * 64);
    const float2* dp = (const float2*)(a_dst + head * 64);
    float s = 0.f, d = 0.f;
#pragma unroll
    for (int i = 0; i < 32; i++) {
        float2 hv = __half22float2(hp[i]);
        float2 av = ap[i], bv = dp[i];
        s += hv.x * av.x + hv.y * av.y;
        d += hv.x * bv.x + hv.y * bv.y;
    }
    g_as[t] = s;
    g_ad[t] = d;
}

// ---------------- gather aggregation: one warp per dst node -------------------
__global__ __launch_bounds__(256) void aggregate_kernel(
    const __half* __restrict__ hfeat, const float* __restrict__ bias,
    float* __restrict__ outp, float* __restrict__ outp2, int N, int relu)
{
    int warp = (blockIdx.x * blockDim.x + threadIdx.x) >> 5;
    if (warp >= N) return;
    int node = warp;
    int lane = threadIdx.x & 31;
    int head = lane >> 4;
    int c = head * 64 + (lane & 15) * 4;

    const float2* as2p = (const float2*)g_as;
    float2 adn = ((const float2*)g_ad)[node];
    float2 asn = as2p[node];
    int beg = g_rowptr[node], end = g_rowptr[node + 1];

    float m0 = lrelu(asn.x + adn.x);
    float m1 = lrelu(asn.y + adn.y);
    for (int i = beg + lane; i < end; i += 32) {
        int s = g_col[i];
        float2 a = as2p[s];
        m0 = fmaxf(m0, lrelu(a.x + adn.x));
        m1 = fmaxf(m1, lrelu(a.y + adn.y));
    }
#pragma unroll
    for (int o = 16; o; o >>= 1) {
        m0 = fmaxf(m0, __shfl_xor_sync(0xffffffffu, m0, o));
        m1 = fmaxf(m1, __shfl_xor_sync(0xffffffffu, m1, o));
    }
    float m = head ? m1 : m0;
    float adh = head ? adn.y : adn.x;

    float denom = 0.f;
    float4 acc = make_float4(0.f, 0.f, 0.f, 0.f);
    {
        float e = lrelu((head ? asn.y : asn.x) + adh);
        float w = __expf(e - m);
        denom += w;
        uint2 u = *(const uint2*)(hfeat + (size_t)node * 128 + c);
        float2 p0 = __half22float2(*(__half2*)&u.x);
        float2 p1 = __half22float2(*(__half2*)&u.y);
        acc.x += w * p0.x; acc.y += w * p0.y; acc.z += w * p1.x; acc.w += w * p1.y;
    }
    for (int i = beg; i < end; i++) {
        int s = g_col[i];
        float2 a = as2p[s];
        float e = lrelu((head ? a.y : a.x) + adh);
        float w = __expf(e - m);
        denom += w;
        uint2 u = *(const uint2*)(hfeat + (size_t)s * 128 + c);
        float2 p0 = __half22float2(*(__half2*)&u.x);
        float2 p1 = __half22float2(*(__half2*)&u.y);
        acc.x += w * p0.x; acc.y += w * p0.y; acc.z += w * p1.x; acc.w += w * p1.y;
    }
    float inv = 1.f / (denom + 1e-16f);
    float4 b4 = *(const float4*)(bias + c);
    float4 o;
    o.x = acc.x * inv + b4.x;
    o.y = acc.y * inv + b4.y;
    o.z = acc.z * inv + b4.z;
    o.w = acc.w * inv + b4.w;
    if (relu) {
        o.x = fmaxf(o.x, 0.f); o.y = fmaxf(o.y, 0.f);
        o.z = fmaxf(o.z, 0.f); o.w = fmaxf(o.w, 0.f);
    }
    *(float4*)(outp + (size_t)node * 128 + c) = o;
    if (outp2) *(float4*)(outp2 + (size_t)node * 128 + c) = o;
}

// ---------------- launch ------------------------------------------------------
extern "C" void kernel_launch(void* const* d_in, const int* in_sizes, int n_in,
                              void* d_out, int out_size)
{
    const float* x   = (const float*)d_in[0];
    const int*   ei  = (const int*)d_in[1];
    const float* W1  = (const float*)d_in[2];
    const float* a_s1 = (const float*)d_in[3];
    const float* a_d1 = (const float*)d_in[4];
    const float* b1  = (const float*)d_in[5];
    const float* W2  = (const float*)d_in[6];
    const float* a_s2 = (const float*)d_in[7];
    const float* a_d2 = (const float*)d_in[8];
    const float* b2  = (const float*)d_in[9];
    const float* lw1 = (const float*)d_in[10];
    const float* lb1 = (const float*)d_in[11];
    const float* lw2 = (const float*)d_in[12];
    const float* lb2 = (const float*)d_in[13];
    const float* lw3 = (const float*)d_in[14];
    const float* lb3 = (const float*)d_in[15];
    float* dout = (float*)d_out;

    int N = in_sizes[0] / 64;
    int E = in_sizes[1] / 2;

    __half *p_hh, *p_z1h;
    float *p_agg, *p_emb, *p_z2;
    cudaGetSymbolAddress((void**)&p_hh, g_hh);
    cudaGetSymbolAddress((void**)&p_agg, g_agg);
    cudaGetSymbolAddress((void**)&p_emb, g_emb);
    cudaGetSymbolAddress((void**)&p_z1h, g_z1h);
    cudaGetSymbolAddress((void**)&p_z2, g_z2);

    const int* src = ei;
    const int* dst = ei + E;

    // --- CSR build ---
    int nb = (N + 1023) / 1024;
    zero_cnt_kernel<<<(N + 255) / 256, 256>>>(N);
    hist_kernel<<<(E + 255) / 256, 256>>>(dst, E);
    scan1_kernel<<<nb, 1024>>>(N);
    scan2_kernel<<<1, 64>>>(nb, N);
    scan3_kernel<<<(N + 255) / 256, 256>>>(N);
    scatter_kernel<<<(E + 255) / 256, 256>>>(src, dst, E);

    int mblk = (N + 127) / 128;

    // output layout: [emb (N*128), logits (N*16)]
    size_t embElems = (size_t)N * 128;
    bool both = (size_t)out_size >= embElems + (size_t)N * 16;
    float* logits_out = both ? (dout + embElems)
                             : (dout + ((size_t)out_size - (size_t)N * 16));
    float* embMirror = both ? dout : nullptr;   // write-only stream into d_out

    // --- GAT layer 1 (h in fp16) ---
    gemm_tc_kernel<<<dim3(1, mblk), 256>>>(x, W1, nullptr, nullptr, p_hh, N, 128, 64, 0);
    coeff_kernel<<<(2 * N + 255) / 256, 256>>>(p_hh, a_s1, a_d1, N);
    aggregate_kernel<<<(N + 7) / 8, 256>>>(p_hh, b1, p_agg, nullptr, N, 1);

    // --- GAT layer 2 (emb -> device scratch + write-only mirror into d_out) ---
    gemm_tc_kernel<<<dim3(1, mblk), 256>>>(p_agg, W2, nullptr, nullptr, p_hh, N, 128, 128, 0);
    coeff_kernel<<<(2 * N + 255) / 256, 256>>>(p_hh, a_s2, a_d2, N);
    aggregate_kernel<<<(N + 7) / 8, 256>>>(p_hh, b2, p_emb, embMirror, N, 1);

    // --- MLP head (fp16 tensor cores; z1 kept fp16) ---
    gemm_fp16_kernel<<<dim3(4, mblk), 256>>>(p_emb, nullptr, lw1, lb1, nullptr, p_z1h, N, 512, 128, 1);
    gemm_fp16_kernel<<<dim3(2, mblk), 256>>>(nullptr, p_z1h, lw2, lb2, p_z2, nullptr, N, 256, 512, 1);
    gemm_logits_kernel<<<(N + 7) / 8, 128>>>(p_z2, lw3, lb3, logits_out, N, 256);
}